// round 4
// baseline (speedup 1.0000x reference)
#include <cuda_runtime.h>
#include <math.h>

#define Hs   128
#define Ws   128
#define Cs   64
#define Os   64
#define HW   16384
#define Q    576          // Cs * 9

typedef unsigned long long u64;

// offsets, layout [k][b*HW] as u64 (dy,dx) pairs : coalesced access both kernels
__device__ u64 g_off[9 * 4 * HW];

// ---------------- packed f32x2 helpers (sm_100+) ----------------
__device__ __forceinline__ u64 pack2(float lo, float hi) {
    u64 r;
    asm("mov.b64 %0, {%1, %2};" : "=l"(r) : "f"(lo), "f"(hi));
    return r;
}
__device__ __forceinline__ void unpack2(u64 v, float& lo, float& hi) {
    asm("mov.b64 {%0, %1}, %2;" : "=f"(lo), "=f"(hi) : "l"(v));
}
__device__ __forceinline__ u64 fma2(u64 a, u64 b, u64 c) {
    u64 d;
    asm("fma.rn.f32x2 %0, %1, %2, %3;" : "=l"(d) : "l"(a), "l"(b), "l"(c));
    return d;
}

// ================= Kernel 1: offset conv (3x3, 64 -> 18, pad 1) =================
__global__ void __launch_bounds__(256, 3)
offset_conv_kernel(const float* __restrict__ x,
                   const float* __restrict__ wo,
                   const float* __restrict__ bo) {
    __shared__ float ws[Q * 20];              // padded stride 20 -> aligned LDS.128
    for (int i = threadIdx.x; i < Q * 18; i += 256) {
        int q  = i / 18;
        int oc = i - q * 18;
        ws[q * 20 + oc] = wo[oc * Q + q];
    }
    __syncthreads();

    int p = blockIdx.x * 256 + threadIdx.x;
    int w = p & 127;
    int h = (p >> 7) & 127;
    int b = p >> 14;
    const float* xb = x + (size_t)b * Cs * HW;

    u64 acc[9];
#pragma unroll
    for (int j = 0; j < 9; j++) acc[j] = pack2(bo[2 * j], bo[2 * j + 1]);

#pragma unroll 1
    for (int k = 0; k < 9; k++) {
        int kh = k / 3, kw = k - kh * 3;
        int iy = h - 1 + kh;
        int ix = w - 1 + kw;
        float vf = (iy >= 0 && iy < Hs && ix >= 0 && ix < Ws) ? 1.0f : 0.0f;
        int cy = min(max(iy, 0), Hs - 1);
        int cx = min(max(ix, 0), Ws - 1);
        const float* xp = xb + cy * Ws + cx;
#pragma unroll 2
        for (int c = 0; c < Cs; c++) {
            float val = __ldg(xp + c * HW) * vf;
            u64 s2 = pack2(val, val);
            const float* wr = &ws[(c * 9 + k) * 20];
            ulonglong2 w01 = *(const ulonglong2*)(wr);
            ulonglong2 w23 = *(const ulonglong2*)(wr + 4);
            ulonglong2 w45 = *(const ulonglong2*)(wr + 8);
            ulonglong2 w67 = *(const ulonglong2*)(wr + 12);
            u64        w8  = *(const u64*)(wr + 16);
            acc[0] = fma2(s2, w01.x, acc[0]);
            acc[1] = fma2(s2, w01.y, acc[1]);
            acc[2] = fma2(s2, w23.x, acc[2]);
            acc[3] = fma2(s2, w23.y, acc[3]);
            acc[4] = fma2(s2, w45.x, acc[4]);
            acc[5] = fma2(s2, w45.y, acc[5]);
            acc[6] = fma2(s2, w67.x, acc[6]);
            acc[7] = fma2(s2, w67.y, acc[7]);
            acc[8] = fma2(s2, w8,    acc[8]);
        }
    }

#pragma unroll
    for (int k = 0; k < 9; k++) g_off[k * 4 * HW + p] = acc[k];
}

// ================= Kernel 2: deformable conv (fused, output-split) =================
// 512 threads/CTA, 256 pixels/CTA. Half-warp output split:
//   lanes 0-15  -> 16 consecutive pixels, outputs  0-31
//   lanes 16-31 -> SAME 16 pixels,        outputs 32-63
// LDG addresses duplicate across halves (L1 dedups lines). acc = 16 u64 only,
// killing the register spills of the previous version.
__global__ void __launch_bounds__(512, 1)
deform_conv_kernel(const float* __restrict__ x,
                   const float* __restrict__ wd,
                   const float* __restrict__ bd,
                   float* __restrict__ out) {
    extern __shared__ float ws[];   // [q][o] : 576*64 floats = 147456 B
    for (int i = threadIdx.x; i < Q * Os; i += 512) {
        int q = i >> 6;
        int o = i & 63;
        ws[i] = wd[o * Q + q];
    }
    __syncthreads();

    int t    = threadIdx.x;
    int warp = t >> 5;
    int lane = t & 31;
    int o0   = (lane >> 4) << 5;                 // 0 or 32
    int p    = blockIdx.x * 256 + warp * 16 + (lane & 15);
    int w = p & 127;
    int h = (p >> 7) & 127;
    int b = p >> 14;
    const float* xb = x + (size_t)b * Cs * HW;

    u64 acc[16];
    const float2* bd2 = (const float2*)(bd + o0);
#pragma unroll
    for (int j = 0; j < 16; j++) { float2 tv = bd2[j]; acc[j] = pack2(tv.x, tv.y); }

#pragma unroll 1
    for (int k = 0; k < 9; k++) {
        int kh = k / 3, kw = k - kh * 3;
        float dlo, dhi;
        unpack2(g_off[k * 4 * HW + p], dlo, dhi);   // (dy, dx)
        float py = (float)(h - 1 + kh) + dlo;
        float px = (float)(w - 1 + kw) + dhi;
        float y0f = floorf(py), x0f = floorf(px);
        int y0 = (int)y0f, x0 = (int)x0f;
        int y1 = y0 + 1,   x1 = x0 + 1;
        float wy1 = py - y0f, wy0 = 1.0f - wy1;
        float wx1 = px - x0f, wx0 = 1.0f - wx1;
        float vy0 = (y0 >= 0 && y0 < Hs) ? 1.0f : 0.0f;
        float vy1 = (y1 >= 0 && y1 < Hs) ? 1.0f : 0.0f;
        float vx0 = (x0 >= 0 && x0 < Ws) ? 1.0f : 0.0f;
        float vx1 = (x1 >= 0 && x1 < Ws) ? 1.0f : 0.0f;
        float w00 = wy0 * wx0 * vy0 * vx0;
        float w01 = wy0 * wx1 * vy0 * vx1;
        float w10 = wy1 * wx0 * vy1 * vx0;
        float w11 = wy1 * wx1 * vy1 * vx1;
        int cy0 = min(max(y0, 0), Hs - 1), cy1 = min(max(y1, 0), Hs - 1);
        int cx0 = min(max(x0, 0), Ws - 1), cx1 = min(max(x1, 0), Ws - 1);
        int o00 = cy0 * Ws + cx0, o01 = cy0 * Ws + cx1;
        int o10 = cy1 * Ws + cx0, o11 = cy1 * Ws + cx1;

        const float* xc = xb;
        const char*  wp = (const char*)(ws + k * 64 + o0);
#pragma unroll 2
        for (int c = 0; c < Cs; c++) {
            float s = fmaf(w00, __ldg(xc + o00),
                      fmaf(w01, __ldg(xc + o01),
                      fmaf(w10, __ldg(xc + o10), w11 * __ldg(xc + o11))));
            u64 s2 = pack2(s, s);
            const ulonglong2* wr = (const ulonglong2*)wp;
#pragma unroll
            for (int j = 0; j < 8; j++) {
                ulonglong2 ww = wr[j];
                acc[2 * j]     = fma2(s2, ww.x, acc[2 * j]);
                acc[2 * j + 1] = fma2(s2, ww.y, acc[2 * j + 1]);
            }
            xc += HW;
            wp += 9 * 64 * sizeof(float);
        }
    }

    float* op = out + (size_t)b * Os * HW + (size_t)(o0)*HW + h * Ws + w;
#pragma unroll
    for (int j = 0; j < 16; j++) {
        float a0, a1;
        unpack2(acc[j], a0, a1);
        op[(2 * j) * HW]     = a0;
        op[(2 * j + 1) * HW] = a1;
    }
}

// ---------------- harness entry ----------------
extern "C" void kernel_launch(void* const* d_in, const int* in_sizes, int n_in,
                              void* d_out, int out_size) {
    const float* x  = (const float*)d_in[0];   // [4,64,128,128]
    const float* wo = (const float*)d_in[1];   // [18,64,3,3]
    const float* bo = (const float*)d_in[2];   // [18]
    const float* wd = (const float*)d_in[3];   // [64,64,3,3]
    const float* bd = (const float*)d_in[4];   // [64]
    float* out = (float*)d_out;                // [4,64,128,128]

    int gem_smem = Q * Os * (int)sizeof(float);   // 147456
    cudaFuncSetAttribute(deform_conv_kernel,
                         cudaFuncAttributeMaxDynamicSharedMemorySize, gem_smem);

    offset_conv_kernel<<<256, 256>>>(x, wo, bo);
    deform_conv_kernel<<<256, 512, gem_smem>>>(x, wd, bd, out);
}

// round 5
// speedup vs baseline: 1.1929x; 1.1929x over previous
#include <cuda_runtime.h>
#include <math.h>

#define Hs   128
#define Ws   128
#define Cs   64
#define Os   64
#define HW   16384
#define Q    576          // Cs * 9
#define SROW 132          // padded S row (floats)

typedef unsigned long long u64;

// offsets, layout [k][b*HW] as u64 (dy,dx) pairs
__device__ u64   g_off[9 * 4 * HW];
// transposed deform weights: wT[k][c][o]
__device__ float g_wT[9 * 64 * 64];

// ---------------- packed f32x2 helpers (sm_100+) ----------------
__device__ __forceinline__ u64 pack2(float lo, float hi) {
    u64 r;
    asm("mov.b64 %0, {%1, %2};" : "=l"(r) : "f"(lo), "f"(hi));
    return r;
}
__device__ __forceinline__ void unpack2(u64 v, float& lo, float& hi) {
    asm("mov.b64 {%0, %1}, %2;" : "=f"(lo), "=f"(hi) : "l"(v));
}
__device__ __forceinline__ u64 fma2(u64 a, u64 b, u64 c) {
    u64 d;
    asm("fma.rn.f32x2 %0, %1, %2, %3;" : "=l"(d) : "l"(a), "l"(b), "l"(c));
    return d;
}

// ================= Kernel 0: weight transpose =================
__global__ void transpose_w(const float* __restrict__ wd) {
    int i = blockIdx.x * 256 + threadIdx.x;   // 9*64*64 = 36864
    if (i < 9 * 64 * 64) {
        int k = i >> 12;
        int r = i & 4095;
        int c = r >> 6;
        int o = r & 63;
        g_wT[i] = wd[o * Q + c * 9 + k];
    }
}

// ================= Kernel 1: offset conv (3x3, 64 -> 18, pad 1) =================
__global__ void __launch_bounds__(256, 3)
offset_conv_kernel(const float* __restrict__ x,
                   const float* __restrict__ wo,
                   const float* __restrict__ bo) {
    __shared__ float ws[Q * 20];
    for (int i = threadIdx.x; i < Q * 18; i += 256) {
        int q  = i / 18;
        int oc = i - q * 18;
        ws[q * 20 + oc] = wo[oc * Q + q];
    }
    __syncthreads();

    int p = blockIdx.x * 256 + threadIdx.x;
    int w = p & 127;
    int h = (p >> 7) & 127;
    int b = p >> 14;
    const float* xb = x + (size_t)b * Cs * HW;

    u64 acc[9];
#pragma unroll
    for (int j = 0; j < 9; j++) acc[j] = pack2(bo[2 * j], bo[2 * j + 1]);

#pragma unroll 1
    for (int k = 0; k < 9; k++) {
        int kh = k / 3, kw = k - kh * 3;
        int iy = h - 1 + kh;
        int ix = w - 1 + kw;
        float vf = (iy >= 0 && iy < Hs && ix >= 0 && ix < Ws) ? 1.0f : 0.0f;
        int cy = min(max(iy, 0), Hs - 1);
        int cx = min(max(ix, 0), Ws - 1);
        const float* xp = xb + cy * Ws + cx;
#pragma unroll 2
        for (int c = 0; c < Cs; c++) {
            float val = __ldg(xp + c * HW) * vf;
            u64 s2 = pack2(val, val);
            const float* wr = &ws[(c * 9 + k) * 20];
            ulonglong2 w01 = *(const ulonglong2*)(wr);
            ulonglong2 w23 = *(const ulonglong2*)(wr + 4);
            ulonglong2 w45 = *(const ulonglong2*)(wr + 8);
            ulonglong2 w67 = *(const ulonglong2*)(wr + 12);
            u64        w8  = *(const u64*)(wr + 16);
            acc[0] = fma2(s2, w01.x, acc[0]);
            acc[1] = fma2(s2, w01.y, acc[1]);
            acc[2] = fma2(s2, w23.x, acc[2]);
            acc[3] = fma2(s2, w23.y, acc[3]);
            acc[4] = fma2(s2, w45.x, acc[4]);
            acc[5] = fma2(s2, w45.y, acc[5]);
            acc[6] = fma2(s2, w67.x, acc[6]);
            acc[7] = fma2(s2, w67.y, acc[7]);
            acc[8] = fma2(s2, w8,    acc[8]);
        }
    }

#pragma unroll
    for (int k = 0; k < 9; k++) g_off[k * 4 * HW + p] = acc[k];
}

// ---------------- bilinear coordinate setup for kernel position k ----------------
__device__ __forceinline__ void bilin_setup(int k, int h, int spx, int P,
    float& w00, float& w01, float& w10, float& w11,
    int& o00, int& o01, int& o10, int& o11)
{
    int kh = k / 3, kw = k - kh * 3;
    float dlo, dhi;
    unpack2(g_off[k * 4 * HW + P], dlo, dhi);   // (dy, dx)
    float py = (float)(h - 1 + kh) + dlo;
    float px = (float)(spx - 1 + kw) + dhi;
    float y0f = floorf(py), x0f = floorf(px);
    int y0 = (int)y0f, x0 = (int)x0f;
    int y1 = y0 + 1,   x1 = x0 + 1;
    float wy1 = py - y0f, wy0 = 1.0f - wy1;
    float wx1 = px - x0f, wx0 = 1.0f - wx1;
    float vy0 = (y0 >= 0 && y0 < Hs) ? 1.0f : 0.0f;
    float vy1 = (y1 >= 0 && y1 < Hs) ? 1.0f : 0.0f;
    float vx0 = (x0 >= 0 && x0 < Ws) ? 1.0f : 0.0f;
    float vx1 = (x1 >= 0 && x1 < Ws) ? 1.0f : 0.0f;
    w00 = wy0 * wx0 * vy0 * vx0;
    w01 = wy0 * wx1 * vy0 * vx1;
    w10 = wy1 * wx0 * vy1 * vx0;
    w11 = wy1 * wx1 * vy1 * vx1;
    int cy0 = min(max(y0, 0), Hs - 1), cy1 = min(max(y1, 0), Hs - 1);
    int cx0 = min(max(x0, 0), Ws - 1), cx1 = min(max(x1, 0), Ws - 1);
    o00 = cy0 * Ws + cx0; o01 = cy0 * Ws + cx1;
    o10 = cy1 * Ws + cx0; o11 = cy1 * Ws + cx1;
}

// ================= Kernel 2: deformable conv, pipelined staged GEMM =================
// 512 CTAs x 256 threads, 2 CTAs/SM. CTA = one image row (128 px) x 64 outputs.
// Double-buffered S[64][SROW] (sampled values) and Wk[64][64]. One barrier per k.
// Taps for k+1 are LDG'd in 4 chunks, each covered by a 16-step GEMM chunk.
__global__ void __launch_bounds__(256, 2)
deform_conv_kernel(const float* __restrict__ x,
                   const float* __restrict__ bd,
                   float* __restrict__ out) {
    extern __shared__ float sm[];
    float* S  = sm;                    // [2][64][SROW]
    float* Wk = sm + 2 * 64 * SROW;    // [2][4096]

    int t  = threadIdx.x;
    int hb = blockIdx.x;
    int h  = hb & 127;
    int b  = hb >> 7;
    const float* xb = x + (size_t)b * Cs * HW;

    // GEMM mapping: 8px x 4out tiles
    int tx = t & 15, ty = t >> 4;
    int px0 = tx * 8, o0 = ty * 4;

    // sampler mapping: 128 px x 2 channel-groups
    int spx = t & 127;
    int cg  = (t >> 7) * 32;
    int P   = hb * 128 + spx;

    u64 acc[16];
#pragma unroll
    for (int o = 0; o < 4; o++) {
        float bv = bd[o0 + o];
        acc[o * 4 + 0] = acc[o * 4 + 1] = acc[o * 4 + 2] = acc[o * 4 + 3] = pack2(bv, bv);
    }

    // ---------------- prologue: stage k = 0 ----------------
    {
        float4 wreg[4];
        const float4* wsrc = (const float4*)g_wT;
#pragma unroll
        for (int i = 0; i < 4; i++) wreg[i] = __ldg(&wsrc[i * 256 + t]);

        float w00, w01, w10, w11; int o00, o01, o10, o11;
        bilin_setup(0, h, spx, P, w00, w01, w10, w11, o00, o01, o10, o11);

#pragma unroll
        for (int ch = 0; ch < 4; ch++) {
            float tp[8][4];
#pragma unroll
            for (int j = 0; j < 8; j++) {
                const float* xc = xb + (cg + ch * 8 + j) * HW;
                tp[j][0] = __ldg(xc + o00); tp[j][1] = __ldg(xc + o01);
                tp[j][2] = __ldg(xc + o10); tp[j][3] = __ldg(xc + o11);
            }
#pragma unroll
            for (int j = 0; j < 8; j++) {
                float s = fmaf(w00, tp[j][0], fmaf(w01, tp[j][1],
                          fmaf(w10, tp[j][2], w11 * tp[j][3])));
                S[(cg + ch * 8 + j) * SROW + spx] = s;
            }
        }
        float4* wdst = (float4*)Wk;
#pragma unroll
        for (int i = 0; i < 4; i++) wdst[i * 256 + t] = wreg[i];
        __syncthreads();
    }

    // ---------------- main loop over kernel positions ----------------
#pragma unroll 1
    for (int k = 0; k < 9; k++) {
        int cb = k & 1, nb = cb ^ 1;
        const float* Sb  = S  + cb * 64 * SROW;
        const float* Wb  = Wk + cb * 4096;

        if (k < 8) {
            // prefetch W(k+1) into regs
            float4 wreg[4];
            const float4* wsrc = (const float4*)(g_wT + (size_t)(k + 1) * 4096);
#pragma unroll
            for (int i = 0; i < 4; i++) wreg[i] = __ldg(&wsrc[i * 256 + t]);

            float w00, w01, w10, w11; int o00, o01, o10, o11;
            bilin_setup(k + 1, h, spx, P, w00, w01, w10, w11, o00, o01, o10, o11);

#pragma unroll
            for (int ch = 0; ch < 4; ch++) {
                // issue tap loads for k+1 (chunk ch)
                float tp[8][4];
#pragma unroll
                for (int j = 0; j < 8; j++) {
                    const float* xc = xb + (cg + ch * 8 + j) * HW;
                    tp[j][0] = __ldg(xc + o00); tp[j][1] = __ldg(xc + o01);
                    tp[j][2] = __ldg(xc + o10); tp[j][3] = __ldg(xc + o11);
                }
                // GEMM chunk (16 c-steps) covers the tap-load latency
#pragma unroll
                for (int c = ch * 16; c < ch * 16 + 16; c++) {
                    const float* Sp = Sb + c * SROW + px0;
                    ulonglong2 A01 = *(const ulonglong2*)Sp;
                    ulonglong2 A23 = *(const ulonglong2*)(Sp + 4);
                    float4 bw = *(const float4*)(Wb + c * 64 + o0);
                    u64 b0 = pack2(bw.x, bw.x);
                    u64 b1 = pack2(bw.y, bw.y);
                    u64 b2 = pack2(bw.z, bw.z);
                    u64 b3 = pack2(bw.w, bw.w);
                    acc[0]  = fma2(A01.x, b0, acc[0]);
                    acc[1]  = fma2(A01.y, b0, acc[1]);
                    acc[2]  = fma2(A23.x, b0, acc[2]);
                    acc[3]  = fma2(A23.y, b0, acc[3]);
                    acc[4]  = fma2(A01.x, b1, acc[4]);
                    acc[5]  = fma2(A01.y, b1, acc[5]);
                    acc[6]  = fma2(A23.x, b1, acc[6]);
                    acc[7]  = fma2(A23.y, b1, acc[7]);
                    acc[8]  = fma2(A01.x, b2, acc[8]);
                    acc[9]  = fma2(A01.y, b2, acc[9]);
                    acc[10] = fma2(A23.x, b2, acc[10]);
                    acc[11] = fma2(A23.y, b2, acc[11]);
                    acc[12] = fma2(A01.x, b3, acc[12]);
                    acc[13] = fma2(A01.y, b3, acc[13]);
                    acc[14] = fma2(A23.x, b3, acc[14]);
                    acc[15] = fma2(A23.y, b3, acc[15]);
                }
                // combine taps, store into next S buffer
#pragma unroll
                for (int j = 0; j < 8; j++) {
                    float s = fmaf(w00, tp[j][0], fmaf(w01, tp[j][1],
                              fmaf(w10, tp[j][2], w11 * tp[j][3])));
                    S[(nb * 64 + cg + ch * 8 + j) * SROW + spx] = s;
                }
            }
            float4* wdst = (float4*)(Wk + nb * 4096);
#pragma unroll
            for (int i = 0; i < 4; i++) wdst[i * 256 + t] = wreg[i];
        } else {
            // last k: GEMM only
#pragma unroll
            for (int c = 0; c < 64; c++) {
                const float* Sp = Sb + c * SROW + px0;
                ulonglong2 A01 = *(const ulonglong2*)Sp;
                ulonglong2 A23 = *(const ulonglong2*)(Sp + 4);
                float4 bw = *(const float4*)(Wb + c * 64 + o0);
                u64 b0 = pack2(bw.x, bw.x);
                u64 b1 = pack2(bw.y, bw.y);
                u64 b2 = pack2(bw.z, bw.z);
                u64 b3 = pack2(bw.w, bw.w);
                acc[0]  = fma2(A01.x, b0, acc[0]);
                acc[1]  = fma2(A01.y, b0, acc[1]);
                acc[2]  = fma2(A23.x, b0, acc[2]);
                acc[3]  = fma2(A23.y, b0, acc[3]);
                acc[4]  = fma2(A01.x, b1, acc[4]);
                acc[5]  = fma2(A01.y, b1, acc[5]);
                acc[6]  = fma2(A23.x, b1, acc[6]);
                acc[7]  = fma2(A23.y, b1, acc[7]);
                acc[8]  = fma2(A01.x, b2, acc[8]);
                acc[9]  = fma2(A01.y, b2, acc[9]);
                acc[10] = fma2(A23.x, b2, acc[10]);
                acc[11] = fma2(A23.y, b2, acc[11]);
                acc[12] = fma2(A01.x, b3, acc[12]);
                acc[13] = fma2(A01.y, b3, acc[13]);
                acc[14] = fma2(A23.x, b3, acc[14]);
                acc[15] = fma2(A23.y, b3, acc[15]);
            }
        }
        __syncthreads();
    }

    // ---------------- epilogue ----------------
    float* op = out + (size_t)b * Os * HW + h * Ws;
#pragma unroll
    for (int o = 0; o < 4; o++) {
#pragma unroll
        for (int pp = 0; pp < 4; pp++) {
            *(u64*)&op[(o0 + o) * HW + px0 + 2 * pp] = acc[o * 4 + pp];
        }
    }
}

// ---------------- harness entry ----------------
extern "C" void kernel_launch(void* const* d_in, const int* in_sizes, int n_in,
                              void* d_out, int out_size) {
    const float* x  = (const float*)d_in[0];   // [4,64,128,128]
    const float* wo = (const float*)d_in[1];   // [18,64,3,3]
    const float* bo = (const float*)d_in[2];   // [18]
    const float* wd = (const float*)d_in[3];   // [64,64,3,3]
    const float* bd = (const float*)d_in[4];   // [64]
    float* out = (float*)d_out;                // [4,64,128,128]

    int gem_smem = (2 * 64 * SROW + 2 * 4096) * (int)sizeof(float);  // 100352
    cudaFuncSetAttribute(deform_conv_kernel,
                         cudaFuncAttributeMaxDynamicSharedMemorySize, gem_smem);

    transpose_w<<<144, 256>>>(wd);
    offset_conv_kernel<<<256, 256>>>(x, wo, bo);
    deform_conv_kernel<<<512, 256, gem_smem>>>(x, bd, out);
}

// round 7
// speedup vs baseline: 2.0118x; 1.6865x over previous
#include <cuda_runtime.h>
#include <cuda_bf16.h>
#include <math.h>

#define Hs   128
#define Ws   128
#define Cs   64
#define Os   64
#define HW   16384
#define Q    576          // Cs * 9

typedef unsigned long long u64;
typedef unsigned int u32;

// offsets, layout [k][b*HW] as u64 (dy,dx) pairs
__device__ u64 g_off[9 * 4 * HW];
// bf16-split deform weights: [k][o][c], hi and lo parts
__device__ __align__(16) __nv_bfloat16 g_whi[9 * 64 * 64];
__device__ __align__(16) __nv_bfloat16 g_wlo[9 * 64 * 64];

// ---------------- packed f32x2 helpers (sm_100+) ----------------
__device__ __forceinline__ u64 pack2(float lo, float hi) {
    u64 r;
    asm("mov.b64 %0, {%1, %2};" : "=l"(r) : "f"(lo), "f"(hi));
    return r;
}
__device__ __forceinline__ void unpack2(u64 v, float& lo, float& hi) {
    asm("mov.b64 {%0, %1}, %2;" : "=f"(lo), "=f"(hi) : "l"(v));
}
__device__ __forceinline__ u64 fma2(u64 a, u64 b, u64 c) {
    u64 d;
    asm("fma.rn.f32x2 %0, %1, %2, %3;" : "=l"(d) : "l"(a), "l"(b), "l"(c));
    return d;
}

#define SMEM_SWIZZLE_128B(o) ((o) ^ (((o) >> 3) & 0x70))

// bf16 HMMA: D(16x8,f32) += A(16x16,bf16,row) * B(16x8,bf16,col)
__device__ __forceinline__ void hmma(float* d, const u32* a, const u32* b) {
    asm volatile(
        "mma.sync.aligned.m16n8k16.row.col.f32.bf16.bf16.f32 "
        "{%0,%1,%2,%3}, {%4,%5,%6,%7}, {%8,%9}, {%0,%1,%2,%3};"
        : "+f"(d[0]), "+f"(d[1]), "+f"(d[2]), "+f"(d[3])
        : "r"(a[0]), "r"(a[1]), "r"(a[2]), "r"(a[3]), "r"(b[0]), "r"(b[1]));
}

// ================= Kernel 0: split deform weights to bf16 hi/lo, layout [k][o][c] =================
__global__ void wsplit_kernel(const float* __restrict__ wd) {
    int i = blockIdx.x * 256 + threadIdx.x;   // 36864
    if (i < 9 * 64 * 64) {
        int k = i >> 12;
        int r = i & 4095;
        int o = r >> 6;
        int c = r & 63;
        float v = wd[o * Q + c * 9 + k];
        __nv_bfloat16 h = __float2bfloat16(v);
        float rem = v - __bfloat162float(h);
        g_whi[i] = h;
        g_wlo[i] = __float2bfloat16(rem);
    }
}

// ================= Kernel 1: offset conv (3x3, 64 -> 18, pad 1) =================
__global__ void __launch_bounds__(256, 3)
offset_conv_kernel(const float* __restrict__ x,
                   const float* __restrict__ wo,
                   const float* __restrict__ bo) {
    __shared__ float ws[Q * 20];
    for (int i = threadIdx.x; i < Q * 18; i += 256) {
        int q  = i / 18;
        int oc = i - q * 18;
        ws[q * 20 + oc] = wo[oc * Q + q];
    }
    __syncthreads();

    int p = blockIdx.x * 256 + threadIdx.x;
    int w = p & 127;
    int h = (p >> 7) & 127;
    int b = p >> 14;
    const float* xb = x + (size_t)b * Cs * HW;

    u64 acc[9];
#pragma unroll
    for (int j = 0; j < 9; j++) acc[j] = pack2(bo[2 * j], bo[2 * j + 1]);

#pragma unroll 1
    for (int k = 0; k < 9; k++) {
        int kh = k / 3, kw = k - kh * 3;
        int iy = h - 1 + kh;
        int ix = w - 1 + kw;
        float vf = (iy >= 0 && iy < Hs && ix >= 0 && ix < Ws) ? 1.0f : 0.0f;
        int cy = min(max(iy, 0), Hs - 1);
        int cx = min(max(ix, 0), Ws - 1);
        const float* xp = xb + cy * Ws + cx;
#pragma unroll 2
        for (int c = 0; c < Cs; c++) {
            float val = __ldg(xp + c * HW) * vf;
            u64 s2 = pack2(val, val);
            const float* wr = &ws[(c * 9 + k) * 20];
            ulonglong2 w01 = *(const ulonglong2*)(wr);
            ulonglong2 w23 = *(const ulonglong2*)(wr + 4);
            ulonglong2 w45 = *(const ulonglong2*)(wr + 8);
            ulonglong2 w67 = *(const ulonglong2*)(wr + 12);
            u64        w8  = *(const u64*)(wr + 16);
            acc[0] = fma2(s2, w01.x, acc[0]);
            acc[1] = fma2(s2, w01.y, acc[1]);
            acc[2] = fma2(s2, w23.x, acc[2]);
            acc[3] = fma2(s2, w23.y, acc[3]);
            acc[4] = fma2(s2, w45.x, acc[4]);
            acc[5] = fma2(s2, w45.y, acc[5]);
            acc[6] = fma2(s2, w67.x, acc[6]);
            acc[7] = fma2(s2, w67.y, acc[7]);
            acc[8] = fma2(s2, w8,    acc[8]);
        }
    }

#pragma unroll
    for (int k = 0; k < 9; k++) g_off[k * 4 * HW + p] = acc[k];
}

// ================= Kernel 2: deformable conv via mma.sync bf16x3 =================
// CTA = one image row: M=128 px, N=64 out, K = 9 chunks of 64 channels.
// SMEM (49152 B):
//   S_hi [128 m][64 k] bf16, 128B rows, SW128   @ 0
//   S_lo                                        @ 16384
//   W_hi [64 n][64 k]  bf16, 128B rows, SW128   @ 32768
//   W_lo                                        @ 40960
// Epilogue reuses bytes [0, 33792) as float O[64][132].
static constexpr int SM_SHI = 0;
static constexpr int SM_SLO = 16384;
static constexpr int SM_WHI = 32768;
static constexpr int SM_WLO = 40960;
static constexpr int SM_TOT = 49152;

__global__ void __launch_bounds__(256, 2)
deform_mma_kernel(const float* __restrict__ x,
                  const float* __restrict__ bd,
                  float* __restrict__ out) {
    extern __shared__ __align__(1024) char smem[];

    int t    = threadIdx.x;
    int wid  = t >> 5;
    int lane = t & 31;
    int g    = lane >> 2;       // 0..7
    int tig  = lane & 3;        // 0..3

    int tile = blockIdx.x;      // 512 tiles = (b,h)
    int h = tile & 127;
    int b = tile >> 7;
    const float* xb = x + (size_t)b * Cs * HW;

    // sampler mapping: 128 px x 2 channel halves
    int spx   = t & 127;
    int cbase = (t >> 7) * 32;
    int P     = tile * 128 + spx;

    // GEMM mapping: warp wid covers pixels [wid*16, wid*16+16)
    int m0 = wid * 16;

    float acc[8][4];
#pragma unroll
    for (int nt = 0; nt < 8; nt++)
#pragma unroll
        for (int j = 0; j < 4; j++) acc[nt][j] = 0.0f;

#pragma unroll 1
    for (int k = 0; k < 9; k++) {
        // ---- stage W chunk: rows n=0..63 of 64 bf16 (128 B), SW128 ----
        for (int j = t; j < 512; j += 256) {
            int n  = j >> 3;
            int c8 = j & 7;
            u32 dst = SMEM_SWIZZLE_128B((u32)(n * 128 + c8 * 16));
            *(uint4*)(smem + SM_WHI + dst) =
                *(const uint4*)(g_whi + k * 4096 + n * 64 + c8 * 8);
            *(uint4*)(smem + SM_WLO + dst) =
                *(const uint4*)(g_wlo + k * 4096 + n * 64 + c8 * 8);
        }

        // ---- sample 32 channels at this k-position, split bf16, STS ----
        {
            int kh = k / 3, kw = k - kh * 3;
            float dlo, dhi;
            unpack2(g_off[k * 4 * HW + P], dlo, dhi);
            float py = (float)(h - 1 + kh) + dlo;
            float px = (float)(spx - 1 + kw) + dhi;
            float y0f = floorf(py), x0f = floorf(px);
            int y0 = (int)y0f, x0 = (int)x0f;
            int y1 = y0 + 1,   x1 = x0 + 1;
            float wy1 = py - y0f, wy0 = 1.0f - wy1;
            float wx1 = px - x0f, wx0 = 1.0f - wx1;
            float vy0 = (y0 >= 0 && y0 < Hs) ? 1.0f : 0.0f;
            float vy1 = (y1 >= 0 && y1 < Hs) ? 1.0f : 0.0f;
            float vx0 = (x0 >= 0 && x0 < Ws) ? 1.0f : 0.0f;
            float vx1 = (x1 >= 0 && x1 < Ws) ? 1.0f : 0.0f;
            float w00 = wy0 * wx0 * vy0 * vx0;
            float w01 = wy0 * wx1 * vy0 * vx1;
            float w10 = wy1 * wx0 * vy1 * vx0;
            float w11 = wy1 * wx1 * vy1 * vx1;
            int cy0 = min(max(y0, 0), Hs - 1), cy1 = min(max(y1, 0), Hs - 1);
            int cx0 = min(max(x0, 0), Ws - 1), cx1 = min(max(x1, 0), Ws - 1);
            int o00 = cy0 * Ws + cx0, o01 = cy0 * Ws + cx1;
            int o10 = cy1 * Ws + cx0, o11 = cy1 * Ws + cx1;

#pragma unroll
            for (int gq = 0; gq < 4; gq++) {
                int c0 = cbase + gq * 8;
                const float* xc = xb + (size_t)c0 * HW;
                float s[8];
#pragma unroll
                for (int j = 0; j < 8; j++) {
                    s[j] = fmaf(w00, __ldg(xc + o00),
                           fmaf(w01, __ldg(xc + o01),
                           fmaf(w10, __ldg(xc + o10), w11 * __ldg(xc + o11))));
                    xc += HW;
                }
                u32 hh[4], ll[4];
#pragma unroll
                for (int j2 = 0; j2 < 4; j2++) {
                    float se = s[2 * j2], so = s[2 * j2 + 1];
                    __nv_bfloat16 he = __float2bfloat16(se);
                    __nv_bfloat16 ho = __float2bfloat16(so);
                    float re = se - __bfloat162float(he);
                    float ro = so - __bfloat162float(ho);
                    __nv_bfloat16 le  = __float2bfloat16(re);
                    __nv_bfloat16 lo2 = __float2bfloat16(ro);
                    hh[j2] = (u32)__bfloat16_as_ushort(he) |
                             ((u32)__bfloat16_as_ushort(ho) << 16);
                    ll[j2] = (u32)__bfloat16_as_ushort(le) |
                             ((u32)__bfloat16_as_ushort(lo2) << 16);
                }
                u32 off = SMEM_SWIZZLE_128B((u32)(spx * 128 + c0 * 2));
                *(uint4*)(smem + SM_SHI + off) = make_uint4(hh[0], hh[1], hh[2], hh[3]);
                *(uint4*)(smem + SM_SLO + off) = make_uint4(ll[0], ll[1], ll[2], ll[3]);
            }
        }
        __syncthreads();

        // ---- GEMM chunk: 4 k16-steps x 8 n-tiles x 3 products ----
#pragma unroll
        for (int ks = 0; ks < 4; ks++) {
            u32 kb = (u32)(ks * 32 + tig * 4);
            u32 r0 = (u32)((m0 + g) * 128);
            u32 r1 = (u32)((m0 + 8 + g) * 128);
            u32 a_hi[4], a_lo[4];
            a_hi[0] = *(const u32*)(smem + SM_SHI + SMEM_SWIZZLE_128B(r0 + kb));
            a_hi[1] = *(const u32*)(smem + SM_SHI + SMEM_SWIZZLE_128B(r1 + kb));
            a_hi[2] = *(const u32*)(smem + SM_SHI + SMEM_SWIZZLE_128B(r0 + kb + 16));
            a_hi[3] = *(const u32*)(smem + SM_SHI + SMEM_SWIZZLE_128B(r1 + kb + 16));
            a_lo[0] = *(const u32*)(smem + SM_SLO + SMEM_SWIZZLE_128B(r0 + kb));
            a_lo[1] = *(const u32*)(smem + SM_SLO + SMEM_SWIZZLE_128B(r1 + kb));
            a_lo[2] = *(const u32*)(smem + SM_SLO + SMEM_SWIZZLE_128B(r0 + kb + 16));
            a_lo[3] = *(const u32*)(smem + SM_SLO + SMEM_SWIZZLE_128B(r1 + kb + 16));
#pragma unroll
            for (int nt = 0; nt < 8; nt++) {
                u32 nr = (u32)((nt * 8 + g) * 128);
                u32 b_hi[2], b_lo[2];
                b_hi[0] = *(const u32*)(smem + SM_WHI + SMEM_SWIZZLE_128B(nr + kb));
                b_hi[1] = *(const u32*)(smem + SM_WHI + SMEM_SWIZZLE_128B(nr + kb + 16));
                b_lo[0] = *(const u32*)(smem + SM_WLO + SMEM_SWIZZLE_128B(nr + kb));
                b_lo[1] = *(const u32*)(smem + SM_WLO + SMEM_SWIZZLE_128B(nr + kb + 16));
                hmma(acc[nt], a_hi, b_hi);
                hmma(acc[nt], a_hi, b_lo);
                hmma(acc[nt], a_lo, b_hi);
            }
        }
        __syncthreads();
    }

    // ---- epilogue: transpose via smem, coalesced store with bias ----
    float* O = (float*)smem;       // [64 n][132 m]
#pragma unroll
    for (int nt = 0; nt < 8; nt++) {
        int n = nt * 8 + tig * 2;
        int m = m0 + g;
        O[n * 132 + m]            = acc[nt][0];
        O[(n + 1) * 132 + m]      = acc[nt][1];
        O[n * 132 + m + 8]        = acc[nt][2];
        O[(n + 1) * 132 + m + 8]  = acc[nt][3];
    }
    __syncthreads();

    float* ob = out + (size_t)b * Os * HW + h * 128;
    for (int i = t; i < 64 * 128; i += 256) {
        int o  = i >> 7;
        int w2 = i & 127;
        ob[(size_t)o * HW + w2] = O[o * 132 + w2] + __ldg(bd + o);
    }
}

// ---------------- harness entry ----------------
extern "C" void kernel_launch(void* const* d_in, const int* in_sizes, int n_in,
                              void* d_out, int out_size) {
    const float* x  = (const float*)d_in[0];   // [4,64,128,128]
    const float* wo = (const float*)d_in[1];   // [18,64,3,3]
    const float* bo = (const float*)d_in[2];   // [18]
    const float* wd = (const float*)d_in[3];   // [64,64,3,3]
    const float* bd = (const float*)d_in[4];   // [64]
    float* out = (float*)d_out;                // [4,64,128,128]

    cudaFuncSetAttribute(deform_mma_kernel,
                         cudaFuncAttributeMaxDynamicSharedMemorySize, SM_TOT);

    wsplit_kernel<<<144, 256>>>(wd);
    offset_conv_kernel<<<256, 256>>>(x, wo, bo);
    deform_mma_kernel<<<512, 256, SM_TOT>>>(x, bd, out);
}

// round 8
// speedup vs baseline: 2.3092x; 1.1479x over previous
#include <cuda_runtime.h>
#include <cuda_bf16.h>
#include <math.h>

#define Hs   128
#define Ws   128
#define Cs   64
#define Os   64
#define HW   16384
#define Q    576          // Cs * 9
#define NP   24           // padded N for offset conv (18 -> 24)

typedef unsigned long long u64;
typedef unsigned int u32;

// offsets, layout [k][b*HW] as u64 (dy,dx) pairs
__device__ u64 g_off[9 * 4 * HW];
// bf16-split deform weights: [k][o][c]
__device__ __align__(16) __nv_bfloat16 g_whi[9 * 64 * 64];
__device__ __align__(16) __nv_bfloat16 g_wlo[9 * 64 * 64];
// bf16-split offset-conv weights: [k][n(24, padded)][c]
__device__ __align__(16) __nv_bfloat16 g_wohi[9 * NP * 64];
__device__ __align__(16) __nv_bfloat16 g_wolo[9 * NP * 64];

// ---------------- helpers ----------------
__device__ __forceinline__ u64 pack2(float lo, float hi) {
    u64 r;
    asm("mov.b64 %0, {%1, %2};" : "=l"(r) : "f"(lo), "f"(hi));
    return r;
}
__device__ __forceinline__ void unpack2(u64 v, float& lo, float& hi) {
    asm("mov.b64 {%0, %1}, %2;" : "=f"(lo), "=f"(hi) : "l"(v));
}

#define SMEM_SWIZZLE_128B(o) ((o) ^ (((o) >> 3) & 0x70))

// bf16 HMMA: D(16x8,f32) += A(16x16,bf16,row) * B(16x8,bf16,col)
__device__ __forceinline__ void hmma(float* d, const u32* a, const u32* b) {
    asm volatile(
        "mma.sync.aligned.m16n8k16.row.col.f32.bf16.bf16.f32 "
        "{%0,%1,%2,%3}, {%4,%5,%6,%7}, {%8,%9}, {%0,%1,%2,%3};"
        : "+f"(d[0]), "+f"(d[1]), "+f"(d[2]), "+f"(d[3])
        : "r"(a[0]), "r"(a[1]), "r"(a[2]), "r"(a[3]), "r"(b[0]), "r"(b[1]));
}

__device__ __forceinline__ void split_bf16(float v, __nv_bfloat16& h, __nv_bfloat16& l) {
    h = __float2bfloat16(v);
    l = __float2bfloat16(v - __bfloat162float(h));
}

// ================= Kernel 0: split both weight sets to bf16 hi/lo =================
// deform: g_whi/g_wlo [k][o][c] (36864 elems); offset: g_wohi/g_wolo [k][n<24][c] (13824)
__global__ void wsplit_kernel(const float* __restrict__ wd,
                              const float* __restrict__ wo) {
    int i = blockIdx.x * 256 + threadIdx.x;
    if (i < 9 * 64 * 64) {
        int k = i >> 12;
        int r = i & 4095;
        int o = r >> 6;
        int c = r & 63;
        float v = wd[o * Q + c * 9 + k];
        __nv_bfloat16 h, l;
        split_bf16(v, h, l);
        g_whi[i] = h;
        g_wlo[i] = l;
    } else if (i < 9 * 64 * 64 + 9 * NP * 64) {
        int j = i - 9 * 64 * 64;
        int k = j / (NP * 64);
        int r = j - k * (NP * 64);
        int n = r >> 6;
        int c = r & 63;
        float v = (n < 18) ? wo[n * Q + c * 9 + k] : 0.0f;
        __nv_bfloat16 h, l;
        split_bf16(v, h, l);
        g_wohi[j] = h;
        g_wolo[j] = l;
    }
}

// ================= Kernel 1: offset conv via mma.sync bf16x3 =================
// CTA = one image row: M=128 px, N=24 (18 real), K = 9 chunks of 64 channels.
// SMEM: S_hi[128][64]bf16 @0 (16384), S_lo @16384, W_hi[24][64] @32768 (3072),
//       W_lo @35840. Epilogue reuses [0,12672) as float O[24][132].
static constexpr int O_SHI = 0;
static constexpr int O_SLO = 16384;
static constexpr int O_WHI = 32768;
static constexpr int O_WLO = 35840;
static constexpr int O_TOT = 38912;

__global__ void __launch_bounds__(256, 2)
offset_mma_kernel(const float* __restrict__ x,
                  const float* __restrict__ bo) {
    extern __shared__ __align__(1024) char smem[];

    int t    = threadIdx.x;
    int wid  = t >> 5;
    int lane = t & 31;
    int g    = lane >> 2;
    int tig  = lane & 3;

    int tile = blockIdx.x;
    int h = tile & 127;
    int b = tile >> 7;
    const float* xb = x + (size_t)b * Cs * HW;

    int spx   = t & 127;
    int cbase = (t >> 7) * 32;
    int m0    = wid * 16;

    float acc[3][4];
#pragma unroll
    for (int nt = 0; nt < 3; nt++)
#pragma unroll
        for (int j = 0; j < 4; j++) acc[nt][j] = 0.0f;

#pragma unroll 1
    for (int k = 0; k < 9; k++) {
        // stage W chunk: 24 rows x 128 B, SW128
        if (t < 192) {
            int n  = t >> 3;
            int c8 = t & 7;
            u32 dst = SMEM_SWIZZLE_128B((u32)(n * 128 + c8 * 16));
            *(uint4*)(smem + O_WHI + dst) =
                *(const uint4*)(g_wohi + k * NP * 64 + n * 64 + c8 * 8);
            *(uint4*)(smem + O_WLO + dst) =
                *(const uint4*)(g_wolo + k * NP * 64 + n * 64 + c8 * 8);
        }

        // shifted-window "sampling": S[px][c] = x[c][h-1+kh][spx-1+kw] (zero pad)
        {
            int kh = k / 3, kw = k - kh * 3;
            int iy = h - 1 + kh;
            int ix = spx - 1 + kw;
            float vf = (iy >= 0 && iy < Hs && ix >= 0 && ix < Ws) ? 1.0f : 0.0f;
            int cy = min(max(iy, 0), Hs - 1);
            int cx = min(max(ix, 0), Ws - 1);
            const float* xp = xb + cy * Ws + cx;

#pragma unroll
            for (int gq = 0; gq < 4; gq++) {
                int c0 = cbase + gq * 8;
                const float* xc = xp + (size_t)c0 * HW;
                u32 hh[4], ll[4];
#pragma unroll
                for (int j2 = 0; j2 < 4; j2++) {
                    float se = __ldg(xc) * vf;              xc += HW;
                    float so = __ldg(xc) * vf;              xc += HW;
                    __nv_bfloat16 he, le, ho, lo2;
                    split_bf16(se, he, le);
                    split_bf16(so, ho, lo2);
                    hh[j2] = (u32)__bfloat16_as_ushort(he) |
                             ((u32)__bfloat16_as_ushort(ho) << 16);
                    ll[j2] = (u32)__bfloat16_as_ushort(le) |
                             ((u32)__bfloat16_as_ushort(lo2) << 16);
                }
                u32 off = SMEM_SWIZZLE_128B((u32)(spx * 128 + c0 * 2));
                *(uint4*)(smem + O_SHI + off) = make_uint4(hh[0], hh[1], hh[2], hh[3]);
                *(uint4*)(smem + O_SLO + off) = make_uint4(ll[0], ll[1], ll[2], ll[3]);
            }
        }
        __syncthreads();

        // GEMM chunk: 4 k16-steps x 3 n-tiles x 3 products
#pragma unroll
        for (int ks = 0; ks < 4; ks++) {
            u32 kb = (u32)(ks * 32 + tig * 4);
            u32 r0 = (u32)((m0 + g) * 128);
            u32 r1 = (u32)((m0 + 8 + g) * 128);
            u32 a_hi[4], a_lo[4];
            a_hi[0] = *(const u32*)(smem + O_SHI + SMEM_SWIZZLE_128B(r0 + kb));
            a_hi[1] = *(const u32*)(smem + O_SHI + SMEM_SWIZZLE_128B(r1 + kb));
            a_hi[2] = *(const u32*)(smem + O_SHI + SMEM_SWIZZLE_128B(r0 + kb + 16));
            a_hi[3] = *(const u32*)(smem + O_SHI + SMEM_SWIZZLE_128B(r1 + kb + 16));
            a_lo[0] = *(const u32*)(smem + O_SLO + SMEM_SWIZZLE_128B(r0 + kb));
            a_lo[1] = *(const u32*)(smem + O_SLO + SMEM_SWIZZLE_128B(r1 + kb));
            a_lo[2] = *(const u32*)(smem + O_SLO + SMEM_SWIZZLE_128B(r0 + kb + 16));
            a_lo[3] = *(const u32*)(smem + O_SLO + SMEM_SWIZZLE_128B(r1 + kb + 16));
#pragma unroll
            for (int nt = 0; nt < 3; nt++) {
                u32 nr = (u32)((nt * 8 + g) * 128);
                u32 b_hi[2], b_lo[2];
                b_hi[0] = *(const u32*)(smem + O_WHI + SMEM_SWIZZLE_128B(nr + kb));
                b_hi[1] = *(const u32*)(smem + O_WHI + SMEM_SWIZZLE_128B(nr + kb + 16));
                b_lo[0] = *(const u32*)(smem + O_WLO + SMEM_SWIZZLE_128B(nr + kb));
                b_lo[1] = *(const u32*)(smem + O_WLO + SMEM_SWIZZLE_128B(nr + kb + 16));
                hmma(acc[nt], a_hi, b_hi);
                hmma(acc[nt], a_hi, b_lo);
                hmma(acc[nt], a_lo, b_hi);
            }
        }
        __syncthreads();
    }

    // epilogue: transpose via smem, pack (dy,dx) pairs into g_off[k][P]
    float* O = (float*)smem;       // [24 n][132 m]
#pragma unroll
    for (int nt = 0; nt < 3; nt++) {
        int n = nt * 8 + tig * 2;
        int m = m0 + g;
        O[n * 132 + m]            = acc[nt][0];
        O[(n + 1) * 132 + m]      = acc[nt][1];
        O[n * 132 + m + 8]        = acc[nt][2];
        O[(n + 1) * 132 + m + 8]  = acc[nt][3];
    }
    __syncthreads();

    int Pbase = tile * 128;
    for (int i = t; i < 9 * 128; i += 256) {
        int k2 = i >> 7;
        int m  = i & 127;
        float dy = O[(2 * k2) * 132 + m]     + __ldg(bo + 2 * k2);
        float dx = O[(2 * k2 + 1) * 132 + m] + __ldg(bo + 2 * k2 + 1);
        g_off[k2 * 4 * HW + Pbase + m] = pack2(dy, dx);
    }
}

// ================= Kernel 2: deformable conv via mma.sync bf16x3 (unchanged) =================
static constexpr int SM_SHI = 0;
static constexpr int SM_SLO = 16384;
static constexpr int SM_WHI = 32768;
static constexpr int SM_WLO = 40960;
static constexpr int SM_TOT = 49152;

__global__ void __launch_bounds__(256, 2)
deform_mma_kernel(const float* __restrict__ x,
                  const float* __restrict__ bd,
                  float* __restrict__ out) {
    extern __shared__ __align__(1024) char smem[];

    int t    = threadIdx.x;
    int wid  = t >> 5;
    int lane = t & 31;
    int g    = lane >> 2;
    int tig  = lane & 3;

    int tile = blockIdx.x;
    int h = tile & 127;
    int b = tile >> 7;
    const float* xb = x + (size_t)b * Cs * HW;

    int spx   = t & 127;
    int cbase = (t >> 7) * 32;
    int P     = tile * 128 + spx;
    int m0    = wid * 16;

    float acc[8][4];
#pragma unroll
    for (int nt = 0; nt < 8; nt++)
#pragma unroll
        for (int j = 0; j < 4; j++) acc[nt][j] = 0.0f;

#pragma unroll 1
    for (int k = 0; k < 9; k++) {
        for (int j = t; j < 512; j += 256) {
            int n  = j >> 3;
            int c8 = j & 7;
            u32 dst = SMEM_SWIZZLE_128B((u32)(n * 128 + c8 * 16));
            *(uint4*)(smem + SM_WHI + dst) =
                *(const uint4*)(g_whi + k * 4096 + n * 64 + c8 * 8);
            *(uint4*)(smem + SM_WLO + dst) =
                *(const uint4*)(g_wlo + k * 4096 + n * 64 + c8 * 8);
        }

        {
            int kh = k / 3, kw = k - kh * 3;
            float dlo, dhi;
            unpack2(g_off[k * 4 * HW + P], dlo, dhi);
            float py = (float)(h - 1 + kh) + dlo;
            float px = (float)(spx - 1 + kw) + dhi;
            float y0f = floorf(py), x0f = floorf(px);
            int y0 = (int)y0f, x0 = (int)x0f;
            int y1 = y0 + 1,   x1 = x0 + 1;
            float wy1 = py - y0f, wy0 = 1.0f - wy1;
            float wx1 = px - x0f, wx0 = 1.0f - wx1;
            float vy0 = (y0 >= 0 && y0 < Hs) ? 1.0f : 0.0f;
            float vy1 = (y1 >= 0 && y1 < Hs) ? 1.0f : 0.0f;
            float vx0 = (x0 >= 0 && x0 < Ws) ? 1.0f : 0.0f;
            float vx1 = (x1 >= 0 && x1 < Ws) ? 1.0f : 0.0f;
            float w00 = wy0 * wx0 * vy0 * vx0;
            float w01 = wy0 * wx1 * vy0 * vx1;
            float w10 = wy1 * wx0 * vy1 * vx0;
            float w11 = wy1 * wx1 * vy1 * vx1;
            int cy0 = min(max(y0, 0), Hs - 1), cy1 = min(max(y1, 0), Hs - 1);
            int cx0 = min(max(x0, 0), Ws - 1), cx1 = min(max(x1, 0), Ws - 1);
            int o00 = cy0 * Ws + cx0, o01 = cy0 * Ws + cx1;
            int o10 = cy1 * Ws + cx0, o11 = cy1 * Ws + cx1;

#pragma unroll
            for (int gq = 0; gq < 4; gq++) {
                int c0 = cbase + gq * 8;
                const float* xc = xb + (size_t)c0 * HW;
                float s[8];
#pragma unroll
                for (int j = 0; j < 8; j++) {
                    s[j] = fmaf(w00, __ldg(xc + o00),
                           fmaf(w01, __ldg(xc + o01),
                           fmaf(w10, __ldg(xc + o10), w11 * __ldg(xc + o11))));
                    xc += HW;
                }
                u32 hh[4], ll[4];
#pragma unroll
                for (int j2 = 0; j2 < 4; j2++) {
                    float se = s[2 * j2], so = s[2 * j2 + 1];
                    __nv_bfloat16 he, le, ho, lo2;
                    split_bf16(se, he, le);
                    split_bf16(so, ho, lo2);
                    hh[j2] = (u32)__bfloat16_as_ushort(he) |
                             ((u32)__bfloat16_as_ushort(ho) << 16);
                    ll[j2] = (u32)__bfloat16_as_ushort(le) |
                             ((u32)__bfloat16_as_ushort(lo2) << 16);
                }
                u32 off = SMEM_SWIZZLE_128B((u32)(spx * 128 + c0 * 2));
                *(uint4*)(smem + SM_SHI + off) = make_uint4(hh[0], hh[1], hh[2], hh[3]);
                *(uint4*)(smem + SM_SLO + off) = make_uint4(ll[0], ll[1], ll[2], ll[3]);
            }
        }
        __syncthreads();

#pragma unroll
        for (int ks = 0; ks < 4; ks++) {
            u32 kb = (u32)(ks * 32 + tig * 4);
            u32 r0 = (u32)((m0 + g) * 128);
            u32 r1 = (u32)((m0 + 8 + g) * 128);
            u32 a_hi[4], a_lo[4];
            a_hi[0] = *(const u32*)(smem + SM_SHI + SMEM_SWIZZLE_128B(r0 + kb));
            a_hi[1] = *(const u32*)(smem + SM_SHI + SMEM_SWIZZLE_128B(r1 + kb));
            a_hi[2] = *(const u32*)(smem + SM_SHI + SMEM_SWIZZLE_128B(r0 + kb + 16));
            a_hi[3] = *(const u32*)(smem + SM_SHI + SMEM_SWIZZLE_128B(r1 + kb + 16));
            a_lo[0] = *(const u32*)(smem + SM_SLO + SMEM_SWIZZLE_128B(r0 + kb));
            a_lo[1] = *(const u32*)(smem + SM_SLO + SMEM_SWIZZLE_128B(r1 + kb));
            a_lo[2] = *(const u32*)(smem + SM_SLO + SMEM_SWIZZLE_128B(r0 + kb + 16));
            a_lo[3] = *(const u32*)(smem + SM_SLO + SMEM_SWIZZLE_128B(r1 + kb + 16));
#pragma unroll
            for (int nt = 0; nt < 8; nt++) {
                u32 nr = (u32)((nt * 8 + g) * 128);
                u32 b_hi[2], b_lo[2];
                b_hi[0] = *(const u32*)(smem + SM_WHI + SMEM_SWIZZLE_128B(nr + kb));
                b_hi[1] = *(const u32*)(smem + SM_WHI + SMEM_SWIZZLE_128B(nr + kb + 16));
                b_lo[0] = *(const u32*)(smem + SM_WLO + SMEM_SWIZZLE_128B(nr + kb));
                b_lo[1] = *(const u32*)(smem + SM_WLO + SMEM_SWIZZLE_128B(nr + kb + 16));
                hmma(acc[nt], a_hi, b_hi);
                hmma(acc[nt], a_hi, b_lo);
                hmma(acc[nt], a_lo, b_hi);
            }
        }
        __syncthreads();
    }

    float* O = (float*)smem;       // [64 n][132 m]
#pragma unroll
    for (int nt = 0; nt < 8; nt++) {
        int n = nt * 8 + tig * 2;
        int m = m0 + g;
        O[n * 132 + m]            = acc[nt][0];
        O[(n + 1) * 132 + m]      = acc[nt][1];
        O[n * 132 + m + 8]        = acc[nt][2];
        O[(n + 1) * 132 + m + 8]  = acc[nt][3];
    }
    __syncthreads();

    float* ob = out + (size_t)b * Os * HW + h * 128;
    for (int i = t; i < 64 * 128; i += 256) {
        int o  = i >> 7;
        int w2 = i & 127;
        ob[(size_t)o * HW + w2] = O[o * 132 + w2] + __ldg(bd + o);
    }
}

// ---------------- harness entry ----------------
extern "C" void kernel_launch(void* const* d_in, const int* in_sizes, int n_in,
                              void* d_out, int out_size) {
    const float* x  = (const float*)d_in[0];   // [4,64,128,128]
    const float* wo = (const float*)d_in[1];   // [18,64,3,3]
    const float* bo = (const float*)d_in[2];   // [18]
    const float* wd = (const float*)d_in[3];   // [64,64,3,3]
    const float* bd = (const float*)d_in[4];   // [64]
    float* out = (float*)d_out;                // [4,64,128,128]

    cudaFuncSetAttribute(offset_mma_kernel,
                         cudaFuncAttributeMaxDynamicSharedMemorySize, O_TOT);
    cudaFuncSetAttribute(deform_mma_kernel,
                         cudaFuncAttributeMaxDynamicSharedMemorySize, SM_TOT);

    wsplit_kernel<<<198, 256>>>(wd, wo);
    offset_mma_kernel<<<512, 256, O_TOT>>>(x, bo);
    deform_mma_kernel<<<512, 256, SM_TOT>>>(x, bd, out);
}